// round 6
// baseline (speedup 1.0000x reference)
#include <cuda_runtime.h>
#include <cstdint>

#define NB      32768
#define DIN     784
#define DH      512
#define DOUT    10
#define NSTEPS  25
#define BETA    0.9f
#define THR     1.0f

typedef unsigned long long u64;

// ---------------- static device scratch ----------------
__device__ float g_cur1[(size_t)NB * DH];

// ---------------- f32x2 helpers (sm_100+ family PTX) ----------------
__device__ __forceinline__ u64 pack2(float lo, float hi) {
    u64 r; asm("mov.b64 %0, {%1, %2};" : "=l"(r) : "f"(lo), "f"(hi)); return r;
}
__device__ __forceinline__ void unpack2(u64 v, float& lo, float& hi) {
    asm("mov.b64 {%0, %1}, %2;" : "=f"(lo), "=f"(hi) : "l"(v));
}
__device__ __forceinline__ u64 fma2(u64 a, u64 b, u64 c) {
    u64 d; asm("fma.rn.f32x2 %0, %1, %2, %3;" : "=l"(d) : "l"(a), "l"(b), "l"(c)); return d;
}
__device__ __forceinline__ u64 add2(u64 a, u64 b) {
    u64 d; asm("add.rn.f32x2 %0, %1, %2;" : "=l"(d) : "l"(a), "l"(b)); return d;
}

// ---------------------------------------------------------------------------
// GEMM via packed f32x2 FFMA: g_cur1[m][n] = b1[n] + sum_k x[m][k]*W1[n][k].
// Bit-identical numerics to the R2 fp32 kernel (same sequential-k FFMA chain
// per output, bias added last). CTA 128x256, 256 thr, micro-tile 8x16,
// k-tile 16, double-buffered smem, reg-staged global prefetch.
// Fragment map: m = ty*4 + d*64 + 0..3 (d<2), n = tx*4 + c*64 + 0..3 (c<4)
//  -> A LDS.128 broadcast (2 addrs/warp), B LDS.128 stride-4-words (conflict-free).
// ---------------------------------------------------------------------------
#define BM 128
#define BN 256
#define BK 16
#define GNKT (DIN / BK)       // 49
#define ARS 132               // A smem row stride (words)
#define BRS 260               // B smem row stride (words)
#define SMEM_GEMM ((2 * BK * ARS + 2 * BK * BRS) * 4)   // 50176 B

__global__ void __launch_bounds__(256, 1)
gemm1_f32x2(const float* __restrict__ X,
            const float* __restrict__ W1,
            const float* __restrict__ b1)
{
    extern __shared__ float sm[];
    float (*As)[BK][ARS] = (float (*)[BK][ARS])sm;
    float (*Bs)[BK][BRS] = (float (*)[BK][BRS])(sm + 2 * BK * ARS);

    const int tid = threadIdx.x;
    const int bm = blockIdx.y * BM;
    const int bn = blockIdx.x * BN;
    const int ty = tid >> 4;          // 0..15
    const int tx = tid & 15;          // 0..15

    // global loaders
    const int lmA = tid >> 1, lkA = (tid & 1) * 8;
    const int lmB = tid;
    const float* aptr = X  + (size_t)(bm + lmA) * DIN + lkA;
    const float* bptr = W1 + (size_t)(bn + lmB) * DIN;

    float4 fa0, fa1, fb0, fb1, fb2, fb3;
    fa0 = *(const float4*)(aptr);
    fa1 = *(const float4*)(aptr + 4);
    fb0 = *(const float4*)(bptr);
    fb1 = *(const float4*)(bptr + 4);
    fb2 = *(const float4*)(bptr + 8);
    fb3 = *(const float4*)(bptr + 12);
    #pragma unroll
    for (int q = 0; q < 4; q++) {
        As[0][lkA + q][lmA]     = ((const float*)&fa0)[q];
        As[0][lkA + 4 + q][lmA] = ((const float*)&fa1)[q];
        Bs[0][q][lmB]      = ((const float*)&fb0)[q];
        Bs[0][4 + q][lmB]  = ((const float*)&fb1)[q];
        Bs[0][8 + q][lmB]  = ((const float*)&fb2)[q];
        Bs[0][12 + q][lmB] = ((const float*)&fb3)[q];
    }
    __syncthreads();

    u64 acc[8][8];
    #pragma unroll
    for (int i = 0; i < 8; i++)
        #pragma unroll
        for (int p = 0; p < 8; p++) acc[i][p] = 0ULL;

    for (int kt = 0; kt < GNKT; kt++) {
        const int buf = kt & 1;
        if (kt + 1 < GNKT) {
            const float* ap = aptr + (kt + 1) * BK;
            const float* bp = bptr + (kt + 1) * BK;
            fa0 = *(const float4*)(ap);
            fa1 = *(const float4*)(ap + 4);
            fb0 = *(const float4*)(bp);
            fb1 = *(const float4*)(bp + 4);
            fb2 = *(const float4*)(bp + 8);
            fb3 = *(const float4*)(bp + 12);
        }
        #pragma unroll
        for (int k = 0; k < BK; k++) {
            const float4 av0 = *(const float4*)(&As[buf][k][ty * 4]);
            const float4 av1 = *(const float4*)(&As[buf][k][ty * 4 + 64]);
            u64 b2[8];
            #pragma unroll
            for (int c = 0; c < 4; c++) {
                const ulonglong2 bv = *(const ulonglong2*)(&Bs[buf][k][tx * 4 + c * 64]);
                b2[c * 2]     = bv.x;
                b2[c * 2 + 1] = bv.y;
            }
            const float a[8] = {av0.x, av0.y, av0.z, av0.w, av1.x, av1.y, av1.z, av1.w};
            #pragma unroll
            for (int i = 0; i < 8; i++) {
                const u64 a2 = pack2(a[i], a[i]);
                #pragma unroll
                for (int p = 0; p < 8; p++)
                    acc[i][p] = fma2(a2, b2[p], acc[i][p]);
            }
        }
        if (kt + 1 < GNKT) {
            const int nb = buf ^ 1;
            #pragma unroll
            for (int q = 0; q < 4; q++) {
                As[nb][lkA + q][lmA]     = ((const float*)&fa0)[q];
                As[nb][lkA + 4 + q][lmA] = ((const float*)&fa1)[q];
                Bs[nb][q][lmB]      = ((const float*)&fb0)[q];
                Bs[nb][4 + q][lmB]  = ((const float*)&fb1)[q];
                Bs[nb][8 + q][lmB]  = ((const float*)&fb2)[q];
                Bs[nb][12 + q][lmB] = ((const float*)&fb3)[q];
            }
        }
        __syncthreads();
    }

    // epilogue: bias add (last, like R2) + float4 stores
    float4 bias[4];
    #pragma unroll
    for (int c = 0; c < 4; c++)
        bias[c] = __ldg((const float4*)(b1 + bn + tx * 4 + c * 64));

    #pragma unroll
    for (int i = 0; i < 8; i++) {
        const int m = bm + ty * 4 + (i >> 2) * 64 + (i & 3);
        float* orow = g_cur1 + (size_t)m * DH + bn + tx * 4;
        #pragma unroll
        for (int c = 0; c < 4; c++) {
            float v0, v1, v2, v3;
            unpack2(acc[i][c * 2],     v0, v1);
            unpack2(acc[i][c * 2 + 1], v2, v3);
            float4 v = {v0 + bias[c].x, v1 + bias[c].y, v2 + bias[c].z, v3 + bias[c].w};
            *(float4*)(orow + c * 64) = v;
        }
    }
}

// ---------------------------------------------------------------------------
// Fused 25-step SNN recurrence. One warp owns FOUR rows as two f32x2 pairs.
// W2 stored pre-packed (w,w) as u64 in smem -> one LDS.64 feeds both pairs'
// FFMA2 accumulate (spike-valued multiplier). Reset folded as sel(-1,0)+add2.
// Per-half arithmetic is bit-identical to the scalar R2 kernel.
// ---------------------------------------------------------------------------
__global__ __launch_bounds__(256)
void snn_kernel(const float* __restrict__ W2,
                const float* __restrict__ b2,
                float* __restrict__ out)
{
    __shared__ u64 w2p[DOUT][DH];      // 40 KB, packed (w,w)
    for (int idx = threadIdx.x; idx < DOUT * DH; idx += 256) {
        const float w = W2[idx];
        w2p[idx / DH][idx % DH] = pack2(w, w);
    }
    __syncthreads();

    const int warp = threadIdx.x >> 5;
    const int lane = threadIdx.x & 31;
    const int rbase = (blockIdx.x * 8 + warp) * 4;   // rows rbase..rbase+3

    const u64 BETA2 = pack2(BETA, BETA);

    // pair 0 = rows (rbase, rbase+1), pair 1 = rows (rbase+2, rbase+3)
    u64 cur1p[2][16], mem1p[2][16];
    #pragma unroll
    for (int s = 0; s < 2; s++) {
        const float* cA = g_cur1 + (size_t)(rbase + 2 * s) * DH + lane;
        const float* cB = g_cur1 + (size_t)(rbase + 2 * s + 1) * DH + lane;
        #pragma unroll
        for (int i = 0; i < 16; i++) {
            cur1p[s][i] = pack2(cA[i * 32], cB[i * 32]);
            mem1p[s][i] = 0ULL;
        }
    }

    u64 mem2p[2] = {0ULL, 0ULL};
    const float b2v = (lane < DOUT) ? b2[lane] : 0.f;
    const u64 b2p = pack2(b2v, b2v);
    const size_t MEMOFF = (size_t)NSTEPS * NB * DOUT;

    for (int t = 0; t < NSTEPS; t++) {
        u64 part0[10], part1[10];
        #pragma unroll
        for (int j = 0; j < DOUT; j++) { part0[j] = 0ULL; part1[j] = 0ULL; }

        #pragma unroll
        for (int i = 0; i < 16; i++) {
            // ---- layer-1 LIF, pair 0 ----
            float a0, a1;
            unpack2(mem1p[0][i], a0, a1);
            const u64 rst0 = pack2((a0 > THR) ? -THR : 0.f, (a1 > THR) ? -THR : 0.f);
            const u64 nm0 = add2(fma2(BETA2, mem1p[0][i], cur1p[0][i]), rst0);
            mem1p[0][i] = nm0;
            float s0a, s0b;
            unpack2(nm0, s0a, s0b);
            const u64 spk0 = pack2((s0a > THR) ? 1.f : 0.f, (s0b > THR) ? 1.f : 0.f);

            // ---- layer-1 LIF, pair 1 ----
            float c0, c1;
            unpack2(mem1p[1][i], c0, c1);
            const u64 rst1 = pack2((c0 > THR) ? -THR : 0.f, (c1 > THR) ? -THR : 0.f);
            const u64 nm1 = add2(fma2(BETA2, mem1p[1][i], cur1p[1][i]), rst1);
            mem1p[1][i] = nm1;
            float s1a, s1b;
            unpack2(nm1, s1a, s1b);
            const u64 spk1 = pack2((s1a > THR) ? 1.f : 0.f, (s1b > THR) ? 1.f : 0.f);

            // ---- accumulate cur2 partials: one LDS.64 serves both pairs ----
            const int n = i * 32 + lane;
            #pragma unroll
            for (int j = 0; j < DOUT; j++) {
                const u64 w = w2p[j][n];
                part0[j] = fma2(spk0, w, part0[j]);
                part1[j] = fma2(spk1, w, part1[j]);
            }
        }

        // butterfly reduce (same per-half combine order as the scalar R2 kernel)
        #pragma unroll
        for (int off = 16; off > 0; off >>= 1)
            #pragma unroll
            for (int j = 0; j < DOUT; j++) {
                part0[j] = add2(part0[j], __shfl_xor_sync(0xffffffffu, part0[j], off));
                part1[j] = add2(part1[j], __shfl_xor_sync(0xffffffffu, part1[j], off));
            }

        if (lane < DOUT) {
            const u64 cur2p0 = add2(part0[lane], b2p);
            const u64 cur2p1 = add2(part1[lane], b2p);

            #pragma unroll
            for (int s = 0; s < 2; s++) {
                const u64 cur2 = s ? cur2p1 : cur2p0;
                float m0, m1;
                unpack2(mem2p[s], m0, m1);
                const u64 rst = pack2((m0 > THR) ? -THR : 0.f, (m1 > THR) ? -THR : 0.f);
                const u64 nm = add2(fma2(BETA2, mem2p[s], cur2), rst);
                mem2p[s] = nm;
                float n0, n1;
                unpack2(nm, n0, n1);

                const size_t base = (size_t)t * NB * DOUT;
                const size_t r0 = (size_t)(rbase + 2 * s) * DOUT + lane;
                const size_t r1 = (size_t)(rbase + 2 * s + 1) * DOUT + lane;
                out[base + r0]          = (n0 > THR) ? 1.f : 0.f;
                out[base + r1]          = (n1 > THR) ? 1.f : 0.f;
                out[MEMOFF + base + r0] = n0;
                out[MEMOFF + base + r1] = n1;
            }
        }
    }
}

// ---------------------------------------------------------------------------
extern "C" void kernel_launch(void* const* d_in, const int* in_sizes, int n_in,
                              void* d_out, int out_size)
{
    (void)in_sizes; (void)n_in; (void)out_size;
    const float* x  = (const float*)d_in[0];   // [32768, 784]
    const float* W1 = (const float*)d_in[1];   // [512, 784]
    const float* b1 = (const float*)d_in[2];   // [512]
    const float* W2 = (const float*)d_in[3];   // [10, 512]
    const float* b2 = (const float*)d_in[4];   // [10]
    float* out = (float*)d_out;                // [2, 25, 32768, 10]

    cudaFuncSetAttribute(gemm1_f32x2, cudaFuncAttributeMaxDynamicSharedMemorySize, SMEM_GEMM);
    dim3 ggrid(DH / BN, NB / BM);              // (2, 256)
    gemm1_f32x2<<<ggrid, 256, SMEM_GEMM>>>(x, W1, b1);

    snn_kernel<<<NB / 32, 256>>>(W2, b2, out); // 8 warps x 4 rows per block
}